// round 10
// baseline (speedup 1.0000x reference)
#include <cuda_runtime.h>
#include <cstdint>

// ExtractPatch: B=8, H=W=1024, N=4096 matches, R=8 -> 17x17 patches.
// out[bn][k]        = normalize(img1[b, my1 + k%17 - 8, mx1 + k/17 - 8])   k in [0,289)
// out[bn][289 + k]  = normalize(img2[b, my2 + k%17 - 8, mx2 + k/17 - 8])
// normalize: (p - mean) / (std_ddof1 + 1e-4), zero-padded outside image.
//
// Structure: one warp handles MPW matches with a 2-deep cp.async pipeline:
// gather of match i+1 overlaps processing of match i.

#define D      17
#define PATCH  289
#define HW     1024
#define NMATCH 4096
#define BATCH  8
#define WPB    4
#define THREADS (WPB * 32)
#define MPW    4              // matches per warp (pipeline length)
#define RS     20             // landing row stride in words (5 x float4)
#define IMGW   (D * RS)       // 340 words per image
#define LANDW  (2 * IMGW)     // 680 words per landing buffer

__device__ __forceinline__ uint64_t pack2(float lo, float hi) {
    uint64_t r;
    asm("mov.b64 %0, {%1, %2};" : "=l"(r) : "f"(lo), "f"(hi));
    return r;
}
__device__ __forceinline__ void unpack2(uint64_t v, float& lo, float& hi) {
    asm("mov.b64 {%0, %1}, %2;" : "=f"(lo), "=f"(hi) : "l"(v));
}
__device__ __forceinline__ uint64_t add2(uint64_t a, uint64_t b) {
    uint64_t r;
    asm("add.rn.f32x2 %0, %1, %2;" : "=l"(r) : "l"(a), "l"(b));
    return r;
}
__device__ __forceinline__ uint64_t fma2(uint64_t a, uint64_t b, uint64_t c) {
    uint64_t r;
    asm("fma.rn.f32x2 %0, %1, %2, %3;" : "=l"(r) : "l"(a), "l"(b), "l"(c));
    return r;
}
__device__ __forceinline__ uint64_t shfl_xor2(uint64_t v, int mask) {
    uint32_t lo = (uint32_t)v, hi = (uint32_t)(v >> 32);
    lo = __shfl_xor_sync(0xffffffffu, lo, mask);
    hi = __shfl_xor_sync(0xffffffffu, hi, mask);
    return (uint64_t)lo | ((uint64_t)hi << 32);
}
__device__ __forceinline__ uint32_t smem_u32(const void* p) {
    return (uint32_t)__cvta_generic_to_shared(p);
}
__device__ __forceinline__ void cp_async16(uint32_t dst, const void* src) {
    asm volatile("cp.async.cg.shared.global [%0], [%1], 16;" :: "r"(dst), "l"(src));
}
__device__ __forceinline__ void sts_zero16(uint32_t dst) {
    asm volatile("st.shared.v4.b32 [%0], {%1, %1, %1, %1};" :: "r"(dst), "r"(0u));
}
__device__ __forceinline__ void cp_commit() {
    asm volatile("cp.async.commit_group;" ::: "memory");
}
__device__ __forceinline__ void cp_wait1() {
    asm volatile("cp.async.wait_group 1;" ::: "memory");
}
__device__ __forceinline__ void cp_wait0() {
    asm volatile("cp.async.wait_group 0;" ::: "memory");
}

__global__ __launch_bounds__(THREADS, 7)
void extract_patch_kernel(const float* __restrict__ img1,
                          const float* __restrict__ img2,
                          const int*   __restrict__ matches,
                          float*       __restrict__ out)
{
    // Landing buffers (row-major, double-buffered) + transposed staging.
    __shared__ __align__(16) float Land[WPB][2][LANDW];
    __shared__ __align__(16) float Tr[WPB][580];

    const int warpId = threadIdx.x >> 5;
    const int lane   = threadIdx.x & 31;

    const int wg  = blockIdx.x * WPB + warpId;   // global warp id, 0..8191
    const int bn0 = wg * MPW;                    // first match of this warp
    const int b   = bn0 >> 12;                   // batch (constant across 4)

    const float* __restrict__ ib1 = img1 + (size_t)b * (HW * HW);
    const float* __restrict__ ib2 = img2 + (size_t)b * (HW * HW);

    float* __restrict__ Trw = Tr[warpId];

    // lane -> 3 chunk slots: s = it*32+lane, row = s/5, q = s%5, valid s < 85
    int  rowv[3], qv[3];
    bool pv[3];
    uint32_t soff[3];
    #pragma unroll
    for (int it = 0; it < 3; ++it) {
        const int s = it * 32 + lane;
        rowv[it] = s / 5;
        qv[it]   = s - rowv[it] * 5;
        pv[it]   = (s < 85);
        soff[it] = (uint32_t)(s * 16);
    }

    // prefetch all 4 match coordinate quads
    int4 M[MPW];
    #pragma unroll
    for (int j = 0; j < MPW; ++j)
        M[j] = __ldg((const int4*)(matches + (size_t)(bn0 + j) * 4));

    // gather issue for match j into buffer buf (per-chunk predicated)
    auto issue = [&](int j, float* buf) {
        const int4 mm = M[j];
        const int y1 = mm.y - 8, xa1 = (mm.x - 8) & ~3;
        const int y2 = mm.w - 8, xa2 = (mm.z - 8) & ~3;
        const uint32_t base = smem_u32(buf);
        #pragma unroll
        for (int it = 0; it < 3; ++it) {
            if (!pv[it]) continue;
            const int row = rowv[it];
            const int q4  = qv[it] * 4;
            const int cy1 = y1 + row, cx1 = xa1 + q4;
            const int cy2 = y2 + row, cx2 = xa2 + q4;
            const uint32_t d1 = base + soff[it];
            const uint32_t d2 = d1 + IMGW * 4;
            if (((unsigned)cy1 < HW) & ((unsigned)cx1 <= (HW - 4)))
                cp_async16(d1, ib1 + cy1 * HW + cx1);
            else
                sts_zero16(d1);
            if (((unsigned)cy2 < HW) & ((unsigned)cx2 <= (HW - 4)))
                cp_async16(d2, ib2 + cy2 * HW + cx2);
            else
                sts_zero16(d2);
        }
        cp_commit();
    };

    issue(0, Land[warpId][0]);

    #pragma unroll
    for (int i = 0; i < MPW; ++i) {
        if (i + 1 < MPW) {
            issue(i + 1, Land[warpId][(i + 1) & 1]);
            cp_wait1();                 // match i's gather done
        } else {
            cp_wait0();
        }

        // ---- process match i from Land[warpId][i&1] ----
        const float* buf = Land[warpId][i & 1];
        const int4 mm = M[i];
        const int off1 = (mm.x - 8) & 3;
        const int off2 = (mm.z - 8) & 3;

        uint64_t S = 0, Q = 0;
        #pragma unroll
        for (int it = 0; it < 3; ++it) {
            if (!pv[it]) continue;
            // own-lane chunks: visible after own cp.async wait (no syncwarp needed)
            const float4 va = ((const float4*)buf)[it * 32 + lane];
            const float4 vb = ((const float4*)(buf + IMGW))[it * 32 + lane];
            const int row   = rowv[it];
            const int base4 = qv[it] * 4;
            const float* e1 = (const float*)&va;
            const float* e2 = (const float*)&vb;
            #pragma unroll
            for (int e = 0; e < 4; ++e) {
                const int ca = base4 + e - off1;     // patch col, image 1
                const int cb = base4 + e - off2;     // patch col, image 2
                const bool ok1 = (unsigned)ca < D;
                const bool ok2 = (unsigned)cb < D;
                const float v1 = e1[e];
                const float v2 = e2[e];
                if (ok1) Trw[ca * D + row]         = v1;   // stride-17: conflict-free
                if (ok2) Trw[PATCH + cb * D + row] = v2;
                const uint64_t u = pack2(ok1 ? v1 : 0.f, ok2 ? v2 : 0.f);
                S = add2(S, u);
                Q = fma2(u, u, Q);
            }
        }

        // ---- packed warp reduction ----
        #pragma unroll
        for (int o = 16; o > 0; o >>= 1) {
            S = add2(S, shfl_xor2(S, o));
            Q = add2(Q, shfl_xor2(Q, o));
        }
        float s1, s2, q1, q2;
        unpack2(S, s1, s2);
        unpack2(Q, q1, q2);

        const float mean1 = s1 * (1.0f / PATCH);
        const float mean2 = s2 * (1.0f / PATCH);
        float var1 = fmaxf((q1 - (float)PATCH * mean1 * mean1) * (1.0f / (PATCH - 1)), 0.f);
        float var2 = fmaxf((q2 - (float)PATCH * mean2 * mean2) * (1.0f / (PATCH - 1)), 0.f);
        const float inv1 = 1.0f / (sqrtf(var1) + 1e-4f);
        const float inv2 = 1.0f / (sqrtf(var2) + 1e-4f);
        const float bb1  = -mean1 * inv1;
        const float bb2  = -mean2 * inv2;

        const uint64_t A1 = pack2(inv1, inv1), B1 = pack2(bb1, bb1);
        const uint64_t A2 = pack2(inv2, inv2), B2 = pack2(bb2, bb2);

        __syncwarp();   // Tr scatter (all lanes) -> visible for transposed read

        // ---- normalized write: 289 float2 over 578 contiguous floats ----
        float2* __restrict__ ob = (float2*)(out + (size_t)(bn0 + i) * (2 * PATCH));
        const uint64_t* __restrict__ Ts = (const uint64_t*)Trw;

        #pragma unroll
        for (int t = 0; t < 10; ++t) {
            const int k = t * 32 + lane;      // float2 index, valid k < 289
            if (t < 9 || lane == 0) {
                const uint64_t v = Ts[k];
                uint64_t A, B;
                if (t < 4)      { A = A1; B = B1; }
                else if (t > 4) { A = A2; B = B2; }
                else {
                    // boundary tile: elem 2k patch1 iff k<=144; 2k+1 patch1 iff k<=143
                    const float aLo = (k <= 144) ? inv1 : inv2, bLo = (k <= 144) ? bb1 : bb2;
                    const float aHi = (k <= 143) ? inv1 : inv2, bHi = (k <= 143) ? bb1 : bb2;
                    A = pack2(aLo, aHi); B = pack2(bLo, bHi);
                }
                const uint64_t w = fma2(v, A, B);
                float wlo, whi;
                unpack2(w, wlo, whi);
                __stcs(&ob[k], make_float2(wlo, whi));
            }
        }
        __syncwarp();   // protect Tr from next iteration's scatter
    }
}

extern "C" void kernel_launch(void* const* d_in, const int* in_sizes, int n_in,
                              void* d_out, int out_size)
{
    const float* img1    = (const float*)d_in[0];
    const float* img2    = (const float*)d_in[1];
    const int*   matches = (const int*)d_in[2];
    float*       out     = (float*)d_out;

    const int total_matches = BATCH * NMATCH;                 // 32768
    const int blocks = total_matches / (WPB * MPW);           // 2048

    extract_patch_kernel<<<blocks, THREADS>>>(img1, img2, matches, out);
}